// round 8
// baseline (speedup 1.0000x reference)
#include <cuda_runtime.h>
#include <cuda_fp16.h>

// Bilinear_89361089561016: 3D grid_sample, trilinear, border padding,
// align_corners=False.  B=2, C=1, X=Y=Z=160.
//
// Round 8 (= Round 7 with the 16B-alignment trap fixed): the scratch arrays
// are now uint4[NVOX/2] (16B-aligned by type) viewed as uint2*. Round 7
// declared them uint2[] (8B alignment) and the even-x0 LDG.128 path trapped
// on a misaligned 16B load, leaving the output poisoned (rel_err=1.0).
//
//  - packed[(y*160+z)*160+x] = fp16 quad (v[x][y][z], v[x][y][z1],
//    v[x][y1][z], v[x][y1][z1]); 32.8MB -> L2-resident beside the streams.
//  - x innermost => planes x0,x0+1 adjacent 8B elements: even x0 reads both
//    with ONE aligned LDG.128; odd x0 takes two LDG.64 (usually same line).
//  - pack(b=1) fused into the sample(b=0) launch (disjoint scratch).

#define DIM   160
#define DIM2  (DIM * DIM)                // 25,600
#define NVOX  (DIM * DIM * DIM)          // 4,096,000

// 32.8MB each, uint4 => guaranteed 16B base alignment
__device__ uint4 g_packedA[NVOX / 2];
__device__ uint4 g_packedB[NVOX / 2];

__device__ __forceinline__ unsigned int h2_to_u32(__half2 h) {
    return *reinterpret_cast<unsigned int*>(&h);
}
__device__ __forceinline__ __half2 u32_to_h2(unsigned int u) {
    return *reinterpret_cast<__half2*>(&u);
}
__device__ __forceinline__ unsigned int pack2(float a, float b) {
    return h2_to_u32(__floats2half2_rn(a, b));
}

// ---------------- pack ----------------------------------------------------
// thread i -> (x = i/DIM2, y, z): coalesced reads along z, scattered 8B write
// to packed[(y*DIM+z)*DIM + x].
__device__ __forceinline__ void pack_body(const float* __restrict__ vol,
                                          uint2* __restrict__ packed,
                                          int b, int i)
{
    int z = i % DIM;
    int t = i / DIM;                  // x*DIM + y
    int y = t % DIM;
    int x = t / DIM;

    int z1   = (z < DIM - 1) ? z + 1 : z;
    int yoff = (y < DIM - 1) ? DIM : 0;

    const float* r0 = vol + (long long)b * NVOX + (long long)t * DIM;
    const float* r1 = r0 + yoff;

    uint2 q;
    q.x = pack2(__ldg(r0 + z), __ldg(r0 + z1));   // y0 row: (z, z1)
    q.y = pack2(__ldg(r1 + z), __ldg(r1 + z1));   // y1 row: (z, z1)
    packed[(y * DIM + z) * DIM + x] = q;
}

__global__ __launch_bounds__(256) void pack_kernel(
    const float* __restrict__ vol, int b)
{
    int i = blockIdx.x * blockDim.x + threadIdx.x;
    if (i < NVOX) pack_body(vol, reinterpret_cast<uint2*>(g_packedA), b, i);
}

// ---------------- sample --------------------------------------------------
__device__ __forceinline__ void sample_body(const float* __restrict__ grid,
                                            float* __restrict__ out,
                                            const uint4* __restrict__ packed16,
                                            int b, int i)
{
    const float* g = grid + (long long)b * 3 * NVOX + i;
    float gx = __ldcs(g);             // streaming: don't evict packed volume
    float gy = __ldcs(g + NVOX);
    float gz = __ldcs(g + 2 * NVOX);

    // unnormalize + border clamp:  ((g+1)*160 - 1)*0.5 = 80*g + 79.5
    float cx = fminf(fmaxf(fmaf(gx, 80.0f, 79.5f), 0.0f), 159.0f);
    float cy = fminf(fmaxf(fmaf(gy, 80.0f, 79.5f), 0.0f), 159.0f);
    float cz = fminf(fmaxf(fmaf(gz, 80.0f, 79.5f), 0.0f), 159.0f);

    float x0f = floorf(cx), y0f = floorf(cy), z0f = floorf(cz);
    float wx = cx - x0f, wy = cy - y0f, wz = cz - z0f;

    int x0 = (int)x0f;
    int y0 = (int)y0f;
    int z0 = (int)z0f;

    int idx = (y0 * DIM + z0) * DIM + x0;   // 8B-element index, x innermost
    const uint2* packed8 = reinterpret_cast<const uint2*>(packed16);

    uint2 q0, q1;
    if ((x0 & 1) == 0) {
        // even x0 (<=158): idx even -> 16B aligned; one load, both planes
        uint4 tq = __ldg(packed16 + (idx >> 1));
        q0 = make_uint2(tq.x, tq.y);
        q1 = make_uint2(tq.z, tq.w);
    } else {
        int dx = (x0 < DIM - 1) ? 1 : 0;    // x0=159 -> x1=159
        q0 = __ldg(packed8 + idx);
        q1 = __ldg(packed8 + idx + dx);
    }

    // q.x = (v[y0][z0], v[y0][z1]),  q.y = (v[y1][z0], v[y1][z1])
    float2 a0 = __half22float2(u32_to_h2(q0.x));
    float2 a1 = __half22float2(u32_to_h2(q0.y));
    float2 b0 = __half22float2(u32_to_h2(q1.x));
    float2 b1 = __half22float2(u32_to_h2(q1.y));

    float c00 = fmaf(wz, a0.y - a0.x, a0.x);   // x0, y0
    float c01 = fmaf(wz, a1.y - a1.x, a1.x);   // x0, y1
    float c10 = fmaf(wz, b0.y - b0.x, b0.x);   // x1, y0
    float c11 = fmaf(wz, b1.y - b1.x, b1.x);   // x1, y1

    float p0 = fmaf(wy, c01 - c00, c00);
    float p1 = fmaf(wy, c11 - c10, c10);

    __stcs(out + (long long)b * NVOX + i, fmaf(wx, p1 - p0, p0));
}

__global__ __launch_bounds__(256) void sample_kernel(
    const float* __restrict__ grid, float* __restrict__ out, int b)
{
    int i = blockIdx.x * blockDim.x + threadIdx.x;
    if (i < NVOX) sample_body(grid, out, g_packedB, b, i);
}

// fused: sample(batch 0, packedA)  ||  pack(batch 1 -> packedB)
#define NBLK 16000                       // NVOX / 256
__global__ __launch_bounds__(256) void fused_kernel(
    const float* __restrict__ vol,
    const float* __restrict__ grid, float* __restrict__ out)
{
    int blk = blockIdx.x;
    if (blk < NBLK) {
        int i = blk * 256 + threadIdx.x;
        sample_body(grid, out, g_packedA, 0, i);
    } else {
        int i = (blk - NBLK) * 256 + threadIdx.x;
        pack_body(vol, reinterpret_cast<uint2*>(g_packedB), 1, i);
    }
}

extern "C" void kernel_launch(void* const* d_in, const int* in_sizes, int n_in,
                              void* d_out, int out_size)
{
    const float* vol  = (const float*)d_in[0];   // input1 [2,1,160,160,160]
    const float* grid = (const float*)d_in[1];   // input2 [2,3,160,160,160]
    float* out = (float*)d_out;

    pack_kernel  <<<NBLK,     256>>>(vol, 0);
    fused_kernel <<<2 * NBLK, 256>>>(vol, grid, out);
    sample_kernel<<<NBLK,     256>>>(grid, out, 1);
}

// round 10
// speedup vs baseline: 1.1205x; 1.1205x over previous
#include <cuda_runtime.h>
#include <cuda_fp16.h>

// Bilinear_89361089561016: 3D grid_sample, trilinear, border padding,
// align_corners=False.  B=2, C=1, X=Y=Z=160.
//
// Round 9: same x-innermost 8B-quad layout as R8 (sample phase proven:
// ~27us, L2-resident), but the pack transpose now goes through shared
// memory so its 8B stores coalesce (R8's direct scatter cost 32 store
// wavefronts/warp -> 30.5us per pack; ncu showed DRAM at only 7.9%).
//
//  - packed[(y*160+z)*160+x] = fp16 quad (v[x][y][z], v[x][y][z1],
//    v[x][y1][z], v[x][y1][z1]); 32.8MB -> L2-resident beside the streams.
//  - sample: even x0 -> ONE aligned LDG.128 covers planes x0,x0+1;
//    odd x0 -> two LDG.64 (usually same 128B line).
//  - pack(b=1) fused into the sample(b=0) launch (disjoint scratch).

#define DIM   160
#define DIM2  (DIM * DIM)                // 25,600
#define NVOX  (DIM * DIM * DIM)          // 4,096,000

// 32.8MB each, uint4 => guaranteed 16B base alignment
__device__ uint4 g_packedA[NVOX / 2];
__device__ uint4 g_packedB[NVOX / 2];

__device__ __forceinline__ unsigned int h2_to_u32(__half2 h) {
    return *reinterpret_cast<unsigned int*>(&h);
}
__device__ __forceinline__ __half2 u32_to_h2(unsigned int u) {
    return *reinterpret_cast<__half2*>(&u);
}
__device__ __forceinline__ unsigned int pack2(float a, float b) {
    return h2_to_u32(__floats2half2_rn(a, b));
}

// ---------------- tiled pack (smem transpose) -----------------------------
// One block handles a (32x, 1y, 32z) tile: stage 64 rows (x-local*2 + dy)
// of 33 clamped z-values in smem, then emit 8B quads with x fastest across
// the warp so stores coalesce.
#define PACK_BLOCKS 4000                 // DIM * 5 * 5
struct PackSmem { float sv[64][33]; };

__device__ __forceinline__ void pack_body_tiled(const float* __restrict__ vol,
                                                uint2* __restrict__ packed,
                                                int b, int p, int tid,
                                                PackSmem& s)
{
    int y   = p / 25;
    int rem = p % 25;
    int z0  = (rem / 5) * 32;
    int x0  = (rem % 5) * 32;

    const float* vb = vol + (long long)b * NVOX;

    // load: 64 rows x 33 z (clamped), coalesced along z
    for (int j = tid; j < 64 * 33; j += 256) {
        int row = j / 33;                 // x_local*2 + dy
        int zz  = j % 33;
        int xg  = x0 + (row >> 1);
        int yg  = min(y + (row & 1), DIM - 1);
        int zg  = min(z0 + zz, DIM - 1);
        s.sv[row][zz] = __ldg(vb + (xg * DIM + yg) * DIM + zg);
    }
    __syncthreads();

    // emit: x fastest across warp -> coalesced 8B stores
    int xl = tid & 31;
    int zb = tid >> 5;                    // 0..7
    #pragma unroll
    for (int k = 0; k < 4; k++) {
        int zl = zb + k * 8;
        uint2 q;
        q.x = pack2(s.sv[xl * 2][zl],     s.sv[xl * 2][zl + 1]);     // y0 row
        q.y = pack2(s.sv[xl * 2 + 1][zl], s.sv[xl * 2 + 1][zl + 1]); // y1 row
        packed[(y * DIM + z0 + zl) * DIM + x0 + xl] = q;
    }
}

__global__ __launch_bounds__(256) void pack_kernel(
    const float* __restrict__ vol, int b)
{
    __shared__ PackSmem s;
    pack_body_tiled(vol, reinterpret_cast<uint2*>(g_packedA), b,
                    blockIdx.x, threadIdx.x, s);
}

// ---------------- sample --------------------------------------------------
__device__ __forceinline__ void sample_body(const float* __restrict__ grid,
                                            float* __restrict__ out,
                                            const uint4* __restrict__ packed16,
                                            int b, int i)
{
    const float* g = grid + (long long)b * 3 * NVOX + i;
    float gx = __ldcs(g);             // streaming: don't evict packed volume
    float gy = __ldcs(g + NVOX);
    float gz = __ldcs(g + 2 * NVOX);

    // unnormalize + border clamp:  ((g+1)*160 - 1)*0.5 = 80*g + 79.5
    float cx = fminf(fmaxf(fmaf(gx, 80.0f, 79.5f), 0.0f), 159.0f);
    float cy = fminf(fmaxf(fmaf(gy, 80.0f, 79.5f), 0.0f), 159.0f);
    float cz = fminf(fmaxf(fmaf(gz, 80.0f, 79.5f), 0.0f), 159.0f);

    float x0f = floorf(cx), y0f = floorf(cy), z0f = floorf(cz);
    float wx = cx - x0f, wy = cy - y0f, wz = cz - z0f;

    int x0 = (int)x0f;
    int y0 = (int)y0f;
    int z0 = (int)z0f;

    int idx = (y0 * DIM + z0) * DIM + x0;   // 8B-element index, x innermost
    const uint2* packed8 = reinterpret_cast<const uint2*>(packed16);

    uint2 q0, q1;
    if ((x0 & 1) == 0) {
        // even x0 (<=158): idx even -> 16B aligned; one load, both planes
        uint4 tq = __ldg(packed16 + (idx >> 1));
        q0 = make_uint2(tq.x, tq.y);
        q1 = make_uint2(tq.z, tq.w);
    } else {
        int dx = (x0 < DIM - 1) ? 1 : 0;    // x0=159 -> x1=159
        q0 = __ldg(packed8 + idx);
        q1 = __ldg(packed8 + idx + dx);
    }

    // q.x = (v[y0][z0], v[y0][z1]),  q.y = (v[y1][z0], v[y1][z1])
    float2 a0 = __half22float2(u32_to_h2(q0.x));
    float2 a1 = __half22float2(u32_to_h2(q0.y));
    float2 b0 = __half22float2(u32_to_h2(q1.x));
    float2 b1 = __half22float2(u32_to_h2(q1.y));

    float c00 = fmaf(wz, a0.y - a0.x, a0.x);   // x0, y0
    float c01 = fmaf(wz, a1.y - a1.x, a1.x);   // x0, y1
    float c10 = fmaf(wz, b0.y - b0.x, b0.x);   // x1, y0
    float c11 = fmaf(wz, b1.y - b1.x, b1.x);   // x1, y1

    float p0 = fmaf(wy, c01 - c00, c00);
    float p1 = fmaf(wy, c11 - c10, c10);

    __stcs(out + (long long)b * NVOX + i, fmaf(wx, p1 - p0, p0));
}

__global__ __launch_bounds__(256) void sample_kernel(
    const float* __restrict__ grid, float* __restrict__ out, int b)
{
    int i = blockIdx.x * blockDim.x + threadIdx.x;
    if (i < NVOX) sample_body(grid, out, g_packedB, b, i);
}

// fused: sample(batch 0, packedA)  ||  tiled pack(batch 1 -> packedB)
#define NBLK 16000                       // NVOX / 256
__global__ __launch_bounds__(256) void fused_kernel(
    const float* __restrict__ vol,
    const float* __restrict__ grid, float* __restrict__ out)
{
    __shared__ PackSmem s;
    int blk = blockIdx.x;
    if (blk < NBLK) {
        int i = blk * 256 + threadIdx.x;
        sample_body(grid, out, g_packedA, 0, i);
    } else {
        pack_body_tiled(vol, reinterpret_cast<uint2*>(g_packedB), 1,
                        blk - NBLK, threadIdx.x, s);
    }
}

extern "C" void kernel_launch(void* const* d_in, const int* in_sizes, int n_in,
                              void* d_out, int out_size)
{
    const float* vol  = (const float*)d_in[0];   // input1 [2,1,160,160,160]
    const float* grid = (const float*)d_in[1];   // input2 [2,3,160,160,160]
    float* out = (float*)d_out;

    pack_kernel  <<<PACK_BLOCKS,        256>>>(vol, 0);
    fused_kernel <<<NBLK + PACK_BLOCKS, 256>>>(vol, grid, out);
    sample_kernel<<<NBLK,               256>>>(grid, out, 1);
}

// round 11
// speedup vs baseline: 1.3384x; 1.1945x over previous
#include <cuda_runtime.h>
#include <cuda_fp16.h>

// Bilinear_89361089561016: 3D grid_sample, trilinear, border padding,
// align_corners=False.  B=2, C=1, X=Y=Z=160.
//
// Round 11: x-innermost 8B-quad layout (sample proven ~27us, L2-resident),
// pack rebuilt to be issue-lean:
//   - staging via float4 LDG.128 (shift/mask indexing, no div/mod)
//   - emit via uint4 stores covering an x-pair (2 outputs/store, coalesced)
//   - fused launch schedules pack blocks FIRST so pack(b=1) truly overlaps
//     sample(b=0) (R10 put them last -> serialized tail).

#define DIM   160
#define DIM2  (DIM * DIM)                // 25,600
#define NVOX  (DIM * DIM * DIM)          // 4,096,000

// 32.8MB each, uint4 => guaranteed 16B base alignment
__device__ uint4 g_packedA[NVOX / 2];
__device__ uint4 g_packedB[NVOX / 2];

__device__ __forceinline__ unsigned int h2_to_u32(__half2 h) {
    return *reinterpret_cast<unsigned int*>(&h);
}
__device__ __forceinline__ __half2 u32_to_h2(unsigned int u) {
    return *reinterpret_cast<__half2*>(&u);
}
__device__ __forceinline__ unsigned int pack2(float a, float b) {
    return h2_to_u32(__floats2half2_rn(a, b));
}

// ---------------- tiled pack (smem transpose, vectorized) -----------------
// One block: (32x, 1y, 32z) tile. 64 staged rows (x_local*2 + dy) of 33
// clamped z-values. Stage: 512 float4 loads + 64 tail scalars. Emit: 512
// uint4 stores (x-pair per store), x fastest -> 256B coalesced segments.
#define PACK_BLOCKS 4000                 // DIM * 5 * 5
struct PackSmem { float sv[64][33]; };   // stride 33: emit LDS 2-way max

__device__ __forceinline__ void pack_body_tiled(const float* __restrict__ vol,
                                                uint4* __restrict__ packed16,
                                                int b, int p, int tid,
                                                PackSmem& s)
{
    int y   = p / 25;
    int rem = p % 25;
    int z0  = (rem / 5) * 32;
    int x0  = (rem % 5) * 32;

    const float* vb = vol + (long long)b * NVOX;

    // stage: 64 rows x 8 float4 (z0..z0+31); 16B-aligned since z0 % 32 == 0
    #pragma unroll
    for (int it = tid; it < 512; it += 256) {
        int row = it >> 3;                // x_local*2 + dy
        int c   = it & 7;
        int xg  = x0 + (row >> 1);
        int yg  = min(y + (row & 1), DIM - 1);
        float4 f = __ldg(reinterpret_cast<const float4*>(
                             vb + (xg * DIM + yg) * DIM + z0) + c);
        s.sv[row][c * 4 + 0] = f.x;
        s.sv[row][c * 4 + 1] = f.y;
        s.sv[row][c * 4 + 2] = f.z;
        s.sv[row][c * 4 + 3] = f.w;
    }
    // tail: z0+32 (clamped at the far border)
    if (tid < 64) {
        int row = tid;
        int xg  = x0 + (row >> 1);
        int yg  = min(y + (row & 1), DIM - 1);
        int zg  = min(z0 + 32, DIM - 1);
        s.sv[row][32] = __ldg(vb + (xg * DIM + yg) * DIM + zg);
    }
    __syncthreads();

    // emit: 32 z rows x 16 x-pairs; lanes consecutive in xq -> coalesced
    #pragma unroll
    for (int it = tid; it < 512; it += 256) {
        int zl = it >> 4;
        int xq = it & 15;
        int r  = xq * 4;                  // rows for (x=2xq:y0,y1, x=2xq+1:y0,y1)
        uint4 o;
        o.x = pack2(s.sv[r + 0][zl], s.sv[r + 0][zl + 1]);
        o.y = pack2(s.sv[r + 1][zl], s.sv[r + 1][zl + 1]);
        o.z = pack2(s.sv[r + 2][zl], s.sv[r + 2][zl + 1]);
        o.w = pack2(s.sv[r + 3][zl], s.sv[r + 3][zl + 1]);
        packed16[(((y * DIM) + z0 + zl) * DIM + x0) / 2 + xq] = o;
    }
}

__global__ __launch_bounds__(256) void pack_kernel(
    const float* __restrict__ vol, int b)
{
    __shared__ PackSmem s;
    pack_body_tiled(vol, g_packedA, b, blockIdx.x, threadIdx.x, s);
}

// ---------------- sample --------------------------------------------------
__device__ __forceinline__ void sample_body(const float* __restrict__ grid,
                                            float* __restrict__ out,
                                            const uint4* __restrict__ packed16,
                                            int b, int i)
{
    const float* g = grid + (long long)b * 3 * NVOX + i;
    float gx = __ldcs(g);             // streaming: don't evict packed volume
    float gy = __ldcs(g + NVOX);
    float gz = __ldcs(g + 2 * NVOX);

    // unnormalize + border clamp:  ((g+1)*160 - 1)*0.5 = 80*g + 79.5
    float cx = fminf(fmaxf(fmaf(gx, 80.0f, 79.5f), 0.0f), 159.0f);
    float cy = fminf(fmaxf(fmaf(gy, 80.0f, 79.5f), 0.0f), 159.0f);
    float cz = fminf(fmaxf(fmaf(gz, 80.0f, 79.5f), 0.0f), 159.0f);

    float x0f = floorf(cx), y0f = floorf(cy), z0f = floorf(cz);
    float wx = cx - x0f, wy = cy - y0f, wz = cz - z0f;

    int x0 = (int)x0f;
    int y0 = (int)y0f;
    int z0 = (int)z0f;

    int idx = (y0 * DIM + z0) * DIM + x0;   // 8B-element index, x innermost
    const uint2* packed8 = reinterpret_cast<const uint2*>(packed16);

    uint2 q0, q1;
    if ((x0 & 1) == 0) {
        // even x0 (<=158): idx even -> 16B aligned; one load, both planes
        uint4 tq = __ldg(packed16 + (idx >> 1));
        q0 = make_uint2(tq.x, tq.y);
        q1 = make_uint2(tq.z, tq.w);
    } else {
        int dx = (x0 < DIM - 1) ? 1 : 0;    // x0=159 -> x1=159
        q0 = __ldg(packed8 + idx);
        q1 = __ldg(packed8 + idx + dx);
    }

    // q.x = (v[y0][z0], v[y0][z1]),  q.y = (v[y1][z0], v[y1][z1])
    float2 a0 = __half22float2(u32_to_h2(q0.x));
    float2 a1 = __half22float2(u32_to_h2(q0.y));
    float2 b0 = __half22float2(u32_to_h2(q1.x));
    float2 b1 = __half22float2(u32_to_h2(q1.y));

    float c00 = fmaf(wz, a0.y - a0.x, a0.x);   // x0, y0
    float c01 = fmaf(wz, a1.y - a1.x, a1.x);   // x0, y1
    float c10 = fmaf(wz, b0.y - b0.x, b0.x);   // x1, y0
    float c11 = fmaf(wz, b1.y - b1.x, b1.x);   // x1, y1

    float p0 = fmaf(wy, c01 - c00, c00);
    float p1 = fmaf(wy, c11 - c10, c10);

    __stcs(out + (long long)b * NVOX + i, fmaf(wx, p1 - p0, p0));
}

__global__ __launch_bounds__(256) void sample_kernel(
    const float* __restrict__ grid, float* __restrict__ out, int b)
{
    int i = blockIdx.x * blockDim.x + threadIdx.x;
    if (i < NVOX) sample_body(grid, out, g_packedB, b, i);
}

// fused: pack blocks FIRST (overlap from wave 1), then sample(b=0) blocks
#define NBLK 16000                       // NVOX / 256
__global__ __launch_bounds__(256) void fused_kernel(
    const float* __restrict__ vol,
    const float* __restrict__ grid, float* __restrict__ out)
{
    __shared__ PackSmem s;
    int blk = blockIdx.x;
    if (blk < PACK_BLOCKS) {
        pack_body_tiled(vol, g_packedB, 1, blk, threadIdx.x, s);
    } else {
        int i = (blk - PACK_BLOCKS) * 256 + threadIdx.x;
        sample_body(grid, out, g_packedA, 0, i);
    }
}

extern "C" void kernel_launch(void* const* d_in, const int* in_sizes, int n_in,
                              void* d_out, int out_size)
{
    const float* vol  = (const float*)d_in[0];   // input1 [2,1,160,160,160]
    const float* grid = (const float*)d_in[1];   // input2 [2,3,160,160,160]
    float* out = (float*)d_out;

    pack_kernel  <<<PACK_BLOCKS,        256>>>(vol, 0);
    fused_kernel <<<NBLK + PACK_BLOCKS, 256>>>(vol, grid, out);
    sample_kernel<<<NBLK,               256>>>(grid, out, 1);
}

// round 13
// speedup vs baseline: 1.3789x; 1.0303x over previous
#include <cuda_runtime.h>
#include <cuda_fp16.h>

// Bilinear_89361089561016: 3D grid_sample, trilinear, border padding,
// align_corners=False.  B=2, C=1, X=Y=Z=160.
//
// Round 12: un-fuse (R11's mixed pack/sample kernel cost ~18us of SM-level
// L1 contention + L2 eviction). New schedule:
//   1) pack_both: both batches in one launch; batch0 -> packedA (plain
//      stores, keep L2-resident), batch1 -> packedB (__stcs, evict-first so
//      it does NOT displace packedA). Volume read with __ldcs.
//   2) sample0 on a quiet machine with packedA L2-resident.
//   3) sample1 streams packedB back in (overlapped with its own gathers).
// Sample body unchanged: x-innermost 8B quads, parity-fused gathers
// (~1.5 L1 wavefronts/output), fp16 corners + fp32 lerp math.

#define DIM   160
#define DIM2  (DIM * DIM)                // 25,600
#define NVOX  (DIM * DIM * DIM)          // 4,096,000

// 32.8MB each, uint4 => guaranteed 16B base alignment
__device__ uint4 g_packedA[NVOX / 2];
__device__ uint4 g_packedB[NVOX / 2];

__device__ __forceinline__ unsigned int h2_to_u32(__half2 h) {
    return *reinterpret_cast<unsigned int*>(&h);
}
__device__ __forceinline__ __half2 u32_to_h2(unsigned int u) {
    return *reinterpret_cast<__half2*>(&u);
}
__device__ __forceinline__ unsigned int pack2(float a, float b) {
    return h2_to_u32(__floats2half2_rn(a, b));
}

// ---------------- tiled pack (smem transpose, vectorized) -----------------
// One block: (32x, 1y, 32z) tile. 64 staged rows (x_local*2 + dy) of 33
// clamped z-values. Stage: 512 float4 __ldcs loads + 64 tail scalars.
// Emit: 512 uint4 stores (x-pair per store), coalesced 256B segments.
#define PACK_BLOCKS 4000                 // DIM * 5 * 5 per batch
struct PackSmem { float sv[64][33]; };   // stride 33: emit LDS 2-way max

template <bool STREAM>
__device__ __forceinline__ void pack_body_tiled(const float* __restrict__ vol,
                                                uint4* __restrict__ packed16,
                                                int b, int p, int tid,
                                                PackSmem& s)
{
    int y   = p / 25;
    int rem = p % 25;
    int z0  = (rem / 5) * 32;
    int x0  = (rem % 5) * 32;

    const float* vb = vol + (long long)b * NVOX;

    // stage: 64 rows x 8 float4 (z0..z0+31); 16B-aligned since z0 % 32 == 0
    #pragma unroll
    for (int it = tid; it < 512; it += 256) {
        int row = it >> 3;                // x_local*2 + dy
        int c   = it & 7;
        int xg  = x0 + (row >> 1);
        int yg  = min(y + (row & 1), DIM - 1);
        float4 f = __ldcs(reinterpret_cast<const float4*>(
                              vb + (xg * DIM + yg) * DIM + z0) + c);
        s.sv[row][c * 4 + 0] = f.x;
        s.sv[row][c * 4 + 1] = f.y;
        s.sv[row][c * 4 + 2] = f.z;
        s.sv[row][c * 4 + 3] = f.w;
    }
    // tail: z0+32 (clamped at the far border)
    if (tid < 64) {
        int row = tid;
        int xg  = x0 + (row >> 1);
        int yg  = min(y + (row & 1), DIM - 1);
        int zg  = min(z0 + 32, DIM - 1);
        s.sv[row][32] = __ldcs(vb + (xg * DIM + yg) * DIM + zg);
    }
    __syncthreads();

    // emit: 32 z rows x 16 x-pairs; lanes consecutive in xq -> coalesced
    #pragma unroll
    for (int it = tid; it < 512; it += 256) {
        int zl = it >> 4;
        int xq = it & 15;
        int r  = xq * 4;                  // rows for (2xq:y0,y1, 2xq+1:y0,y1)
        uint4 o;
        o.x = pack2(s.sv[r + 0][zl], s.sv[r + 0][zl + 1]);
        o.y = pack2(s.sv[r + 1][zl], s.sv[r + 1][zl + 1]);
        o.z = pack2(s.sv[r + 2][zl], s.sv[r + 2][zl + 1]);
        o.w = pack2(s.sv[r + 3][zl], s.sv[r + 3][zl + 1]);
        uint4* dst = packed16 + ((((y * DIM) + z0 + zl) * DIM + x0) / 2 + xq);
        if (STREAM) __stcs(dst, o);       // batch1: don't evict packedA
        else        *dst = o;             // batch0: let it stay in L2
    }
}

// both batches in one launch: blocks [0,4000) -> A, [4000,8000) -> B
__global__ __launch_bounds__(256) void pack_both_kernel(
    const float* __restrict__ vol)
{
    __shared__ PackSmem s;
    int blk = blockIdx.x;
    if (blk < PACK_BLOCKS)
        pack_body_tiled<false>(vol, g_packedA, 0, blk, threadIdx.x, s);
    else
        pack_body_tiled<true >(vol, g_packedB, 1, blk - PACK_BLOCKS,
                               threadIdx.x, s);
}

// ---------------- sample --------------------------------------------------
__global__ __launch_bounds__(256) void sample_kernel(
    const float* __restrict__ grid, float* __restrict__ out, int b)
{
    int i = blockIdx.x * blockDim.x + threadIdx.x;
    if (i >= NVOX) return;

    const uint4* packed16 = (b == 0) ? g_packedA : g_packedB;

    const float* g = grid + (long long)b * 3 * NVOX + i;
    float gx = __ldcs(g);             // streaming: don't evict packed volume
    float gy = __ldcs(g + NVOX);
    float gz = __ldcs(g + 2 * NVOX);

    // unnormalize + border clamp:  ((g+1)*160 - 1)*0.5 = 80*g + 79.5
    float cx = fminf(fmaxf(fmaf(gx, 80.0f, 79.5f), 0.0f), 159.0f);
    float cy = fminf(fmaxf(fmaf(gy, 80.0f, 79.5f), 0.0f), 159.0f);
    float cz = fminf(fmaxf(fmaf(gz, 80.0f, 79.5f), 0.0f), 159.0f);

    float x0f = floorf(cx), y0f = floorf(cy), z0f = floorf(cz);
    float wx = cx - x0f, wy = cy - y0f, wz = cz - z0f;

    int x0 = (int)x0f;
    int y0 = (int)y0f;
    int z0 = (int)z0f;

    int idx = (y0 * DIM + z0) * DIM + x0;   // 8B-element index, x innermost
    const uint2* packed8 = reinterpret_cast<const uint2*>(packed16);

    uint2 q0, q1;
    if ((x0 & 1) == 0) {
        // even x0 (<=158): idx even -> 16B aligned; one load, both planes
        uint4 tq = __ldg(packed16 + (idx >> 1));
        q0 = make_uint2(tq.x, tq.y);
        q1 = make_uint2(tq.z, tq.w);
    } else {
        int dx = (x0 < DIM - 1) ? 1 : 0;    // x0=159 -> x1=159
        q0 = __ldg(packed8 + idx);
        q1 = __ldg(packed8 + idx + dx);
    }

    // q.x = (v[y0][z0], v[y0][z1]),  q.y = (v[y1][z0], v[y1][z1])
    float2 a0 = __half22float2(u32_to_h2(q0.x));
    float2 a1 = __half22float2(u32_to_h2(q0.y));
    float2 b0 = __half22float2(u32_to_h2(q1.x));
    float2 b1 = __half22float2(u32_to_h2(q1.y));

    float c00 = fmaf(wz, a0.y - a0.x, a0.x);   // x0, y0
    float c01 = fmaf(wz, a1.y - a1.x, a1.x);   // x0, y1
    float c10 = fmaf(wz, b0.y - b0.x, b0.x);   // x1, y0
    float c11 = fmaf(wz, b1.y - b1.x, b1.x);   // x1, y1

    float p0 = fmaf(wy, c01 - c00, c00);
    float p1 = fmaf(wy, c11 - c10, c10);

    __stcs(out + (long long)b * NVOX + i, fmaf(wx, p1 - p0, p0));
}

#define NBLK 16000                       // NVOX / 256

extern "C" void kernel_launch(void* const* d_in, const int* in_sizes, int n_in,
                              void* d_out, int out_size)
{
    const float* vol  = (const float*)d_in[0];   // input1 [2,1,160,160,160]
    const float* grid = (const float*)d_in[1];   // input2 [2,3,160,160,160]
    float* out = (float*)d_out;

    pack_both_kernel<<<2 * PACK_BLOCKS, 256>>>(vol);
    sample_kernel   <<<NBLK,            256>>>(grid, out, 0);
    sample_kernel   <<<NBLK,            256>>>(grid, out, 1);
}

// round 14
// speedup vs baseline: 1.4048x; 1.0187x over previous
#include <cuda_runtime.h>
#include <cuda_fp16.h>

// Bilinear_89361089561016: 3D grid_sample, trilinear, border padding,
// align_corners=False.  B=2, C=1, X=Y=Z=160.
//
// Round 14: both packed arrays kept L2-resident (65.6MB total < 126MB L2):
// pack_both writes A and B with PLAIN stores (R13 streamed B with __stcs,
// forcing sample1 to re-pull 32.8MB from DRAM), and the two sample passes
// merge into one 32000-block launch. Sample body unchanged: x-innermost
// 8B fp16 quads, parity-fused gathers (~1.5 L1 wf/output), fp32 lerp math.

#define DIM   160
#define DIM2  (DIM * DIM)                // 25,600
#define NVOX  (DIM * DIM * DIM)          // 4,096,000

// 32.8MB each, uint4 => guaranteed 16B base alignment
__device__ uint4 g_packedA[NVOX / 2];
__device__ uint4 g_packedB[NVOX / 2];

__device__ __forceinline__ unsigned int h2_to_u32(__half2 h) {
    return *reinterpret_cast<unsigned int*>(&h);
}
__device__ __forceinline__ __half2 u32_to_h2(unsigned int u) {
    return *reinterpret_cast<__half2*>(&u);
}
__device__ __forceinline__ unsigned int pack2(float a, float b) {
    return h2_to_u32(__floats2half2_rn(a, b));
}

// ---------------- tiled pack (smem transpose, vectorized) -----------------
// One block: (32x, 1y, 32z) tile. 64 staged rows (x_local*2 + dy) of 33
// clamped z-values. Stage: 512 float4 loads + 64 tail scalars. Emit: 512
// uint4 stores (x-pair per store), coalesced 256B segments. Plain stores:
// packed arrays are meant to stay in L2 for the sample pass.
#define PACK_BLOCKS 4000                 // DIM * 5 * 5 per batch
struct PackSmem { float sv[64][33]; };   // stride 33: emit LDS 2-way max

__device__ __forceinline__ void pack_body_tiled(const float* __restrict__ vol,
                                                uint4* __restrict__ packed16,
                                                int b, int p, int tid,
                                                PackSmem& s)
{
    int y   = p / 25;
    int rem = p % 25;
    int z0  = (rem / 5) * 32;
    int x0  = (rem % 5) * 32;

    const float* vb = vol + (long long)b * NVOX;

    // stage: 64 rows x 8 float4 (z0..z0+31); 16B-aligned since z0 % 32 == 0
    #pragma unroll
    for (int it = tid; it < 512; it += 256) {
        int row = it >> 3;                // x_local*2 + dy
        int c   = it & 7;
        int xg  = x0 + (row >> 1);
        int yg  = min(y + (row & 1), DIM - 1);
        float4 f = __ldg(reinterpret_cast<const float4*>(
                             vb + (xg * DIM + yg) * DIM + z0) + c);
        s.sv[row][c * 4 + 0] = f.x;
        s.sv[row][c * 4 + 1] = f.y;
        s.sv[row][c * 4 + 2] = f.z;
        s.sv[row][c * 4 + 3] = f.w;
    }
    // tail: z0+32 (clamped at the far border)
    if (tid < 64) {
        int row = tid;
        int xg  = x0 + (row >> 1);
        int yg  = min(y + (row & 1), DIM - 1);
        int zg  = min(z0 + 32, DIM - 1);
        s.sv[row][32] = __ldg(vb + (xg * DIM + yg) * DIM + zg);
    }
    __syncthreads();

    // emit: 32 z rows x 16 x-pairs; lanes consecutive in xq -> coalesced
    #pragma unroll
    for (int it = tid; it < 512; it += 256) {
        int zl = it >> 4;
        int xq = it & 15;
        int r  = xq * 4;                  // rows for (2xq:y0,y1, 2xq+1:y0,y1)
        uint4 o;
        o.x = pack2(s.sv[r + 0][zl], s.sv[r + 0][zl + 1]);
        o.y = pack2(s.sv[r + 1][zl], s.sv[r + 1][zl + 1]);
        o.z = pack2(s.sv[r + 2][zl], s.sv[r + 2][zl + 1]);
        o.w = pack2(s.sv[r + 3][zl], s.sv[r + 3][zl + 1]);
        packed16[(((y * DIM) + z0 + zl) * DIM + x0) / 2 + xq] = o;
    }
}

// both batches in one launch: blocks [0,4000) -> A, [4000,8000) -> B
__global__ __launch_bounds__(256) void pack_both_kernel(
    const float* __restrict__ vol)
{
    __shared__ PackSmem s;
    int blk = blockIdx.x;
    if (blk < PACK_BLOCKS)
        pack_body_tiled(vol, g_packedA, 0, blk, threadIdx.x, s);
    else
        pack_body_tiled(vol, g_packedB, 1, blk - PACK_BLOCKS, threadIdx.x, s);
}

// ---------------- merged sample (both batches) ----------------------------
#define NBLK 16000                       // NVOX / 256

__global__ __launch_bounds__(256) void sample_kernel(
    const float* __restrict__ grid, float* __restrict__ out)
{
    int blk = blockIdx.x;
    int b   = blk >= NBLK;
    int i   = (blk - b * NBLK) * 256 + threadIdx.x;

    const uint4* packed16 = b ? g_packedB : g_packedA;

    const float* g = grid + (long long)b * 3 * NVOX + i;
    float gx = __ldcs(g);             // streaming: don't evict packed arrays
    float gy = __ldcs(g + NVOX);
    float gz = __ldcs(g + 2 * NVOX);

    // unnormalize + border clamp:  ((g+1)*160 - 1)*0.5 = 80*g + 79.5
    float cx = fminf(fmaxf(fmaf(gx, 80.0f, 79.5f), 0.0f), 159.0f);
    float cy = fminf(fmaxf(fmaf(gy, 80.0f, 79.5f), 0.0f), 159.0f);
    float cz = fminf(fmaxf(fmaf(gz, 80.0f, 79.5f), 0.0f), 159.0f);

    float x0f = floorf(cx), y0f = floorf(cy), z0f = floorf(cz);
    float wx = cx - x0f, wy = cy - y0f, wz = cz - z0f;

    int x0 = (int)x0f;
    int y0 = (int)y0f;
    int z0 = (int)z0f;

    int idx = (y0 * DIM + z0) * DIM + x0;   // 8B-element index, x innermost
    const uint2* packed8 = reinterpret_cast<const uint2*>(packed16);

    uint2 q0, q1;
    if ((x0 & 1) == 0) {
        // even x0 (<=158): idx even -> 16B aligned; one load, both planes
        uint4 tq = __ldg(packed16 + (idx >> 1));
        q0 = make_uint2(tq.x, tq.y);
        q1 = make_uint2(tq.z, tq.w);
    } else {
        int dx = (x0 < DIM - 1) ? 1 : 0;    // x0=159 -> x1=159
        q0 = __ldg(packed8 + idx);
        q1 = __ldg(packed8 + idx + dx);
    }

    // q.x = (v[y0][z0], v[y0][z1]),  q.y = (v[y1][z0], v[y1][z1])
    float2 a0 = __half22float2(u32_to_h2(q0.x));
    float2 a1 = __half22float2(u32_to_h2(q0.y));
    float2 b0 = __half22float2(u32_to_h2(q1.x));
    float2 b1 = __half22float2(u32_to_h2(q1.y));

    float c00 = fmaf(wz, a0.y - a0.x, a0.x);   // x0, y0
    float c01 = fmaf(wz, a1.y - a1.x, a1.x);   // x0, y1
    float c10 = fmaf(wz, b0.y - b0.x, b0.x);   // x1, y0
    float c11 = fmaf(wz, b1.y - b1.x, b1.x);   // x1, y1

    float p0 = fmaf(wy, c01 - c00, c00);
    float p1 = fmaf(wy, c11 - c10, c10);

    __stcs(out + (long long)b * NVOX + i, fmaf(wx, p1 - p0, p0));
}

extern "C" void kernel_launch(void* const* d_in, const int* in_sizes, int n_in,
                              void* d_out, int out_size)
{
    const float* vol  = (const float*)d_in[0];   // input1 [2,1,160,160,160]
    const float* grid = (const float*)d_in[1];   // input2 [2,3,160,160,160]
    float* out = (float*)d_out;

    pack_both_kernel<<<2 * PACK_BLOCKS, 256>>>(vol);
    sample_kernel   <<<2 * NBLK,        256>>>(grid, out);
}

// round 15
// speedup vs baseline: 1.5052x; 1.0715x over previous
#include <cuda_runtime.h>
#include <cuda_fp16.h>

// Bilinear_89361089561016: 3D grid_sample, trilinear, border padding,
// align_corners=False.  B=2, C=1, X=Y=Z=160.
//
// Round 15: sample processes 4 consecutive z-outputs per thread:
//  - grid read as 3x float4 (LDG.128) instead of 12 scalar loads
//  - output written as one float4 store
//  - 4 independent parity-fused gathers in flight per thread (R14 ncu showed
//    the sample latency-bound at issue=34% with no memory roof hit: ~2 loads
//    in flight per warp was too few).
// Pack unchanged (smem-transpose tiles, both packed arrays L2-resident).

#define DIM   160
#define DIM2  (DIM * DIM)                // 25,600
#define NVOX  (DIM * DIM * DIM)          // 4,096,000

// 32.8MB each, uint4 => guaranteed 16B base alignment
__device__ uint4 g_packedA[NVOX / 2];
__device__ uint4 g_packedB[NVOX / 2];

__device__ __forceinline__ unsigned int h2_to_u32(__half2 h) {
    return *reinterpret_cast<unsigned int*>(&h);
}
__device__ __forceinline__ __half2 u32_to_h2(unsigned int u) {
    return *reinterpret_cast<__half2*>(&u);
}
__device__ __forceinline__ unsigned int pack2(float a, float b) {
    return h2_to_u32(__floats2half2_rn(a, b));
}

// ---------------- tiled pack (smem transpose, vectorized) -----------------
#define PACK_BLOCKS 4000                 // DIM * 5 * 5 per batch
struct PackSmem { float sv[64][33]; };   // stride 33: emit LDS 2-way max

__device__ __forceinline__ void pack_body_tiled(const float* __restrict__ vol,
                                                uint4* __restrict__ packed16,
                                                int b, int p, int tid,
                                                PackSmem& s)
{
    int y   = p / 25;
    int rem = p % 25;
    int z0  = (rem / 5) * 32;
    int x0  = (rem % 5) * 32;

    const float* vb = vol + (long long)b * NVOX;

    // stage: 64 rows x 8 float4 (z0..z0+31); 16B-aligned since z0 % 32 == 0
    #pragma unroll
    for (int it = tid; it < 512; it += 256) {
        int row = it >> 3;                // x_local*2 + dy
        int c   = it & 7;
        int xg  = x0 + (row >> 1);
        int yg  = min(y + (row & 1), DIM - 1);
        float4 f = __ldg(reinterpret_cast<const float4*>(
                             vb + (xg * DIM + yg) * DIM + z0) + c);
        s.sv[row][c * 4 + 0] = f.x;
        s.sv[row][c * 4 + 1] = f.y;
        s.sv[row][c * 4 + 2] = f.z;
        s.sv[row][c * 4 + 3] = f.w;
    }
    // tail: z0+32 (clamped at the far border)
    if (tid < 64) {
        int row = tid;
        int xg  = x0 + (row >> 1);
        int yg  = min(y + (row & 1), DIM - 1);
        int zg  = min(z0 + 32, DIM - 1);
        s.sv[row][32] = __ldg(vb + (xg * DIM + yg) * DIM + zg);
    }
    __syncthreads();

    // emit: 32 z rows x 16 x-pairs; lanes consecutive in xq -> coalesced
    #pragma unroll
    for (int it = tid; it < 512; it += 256) {
        int zl = it >> 4;
        int xq = it & 15;
        int r  = xq * 4;                  // rows for (2xq:y0,y1, 2xq+1:y0,y1)
        uint4 o;
        o.x = pack2(s.sv[r + 0][zl], s.sv[r + 0][zl + 1]);
        o.y = pack2(s.sv[r + 1][zl], s.sv[r + 1][zl + 1]);
        o.z = pack2(s.sv[r + 2][zl], s.sv[r + 2][zl + 1]);
        o.w = pack2(s.sv[r + 3][zl], s.sv[r + 3][zl + 1]);
        packed16[(((y * DIM) + z0 + zl) * DIM + x0) / 2 + xq] = o;
    }
}

__global__ __launch_bounds__(256) void pack_both_kernel(
    const float* __restrict__ vol)
{
    __shared__ PackSmem s;
    int blk = blockIdx.x;
    if (blk < PACK_BLOCKS)
        pack_body_tiled(vol, g_packedA, 0, blk, threadIdx.x, s);
    else
        pack_body_tiled(vol, g_packedB, 1, blk - PACK_BLOCKS, threadIdx.x, s);
}

// ---------------- sample: 4 outputs per thread ----------------------------
// one gather (parity-fused) for a single sample point
__device__ __forceinline__ float sample_one(const uint4* __restrict__ packed16,
                                            float gx, float gy, float gz)
{
    // unnormalize + border clamp:  ((g+1)*160 - 1)*0.5 = 80*g + 79.5
    float cx = fminf(fmaxf(fmaf(gx, 80.0f, 79.5f), 0.0f), 159.0f);
    float cy = fminf(fmaxf(fmaf(gy, 80.0f, 79.5f), 0.0f), 159.0f);
    float cz = fminf(fmaxf(fmaf(gz, 80.0f, 79.5f), 0.0f), 159.0f);

    float x0f = floorf(cx), y0f = floorf(cy), z0f = floorf(cz);
    float wx = cx - x0f, wy = cy - y0f, wz = cz - z0f;

    int x0 = (int)x0f;
    int y0 = (int)y0f;
    int z0 = (int)z0f;

    int idx = (y0 * DIM + z0) * DIM + x0;   // 8B-element index, x innermost
    const uint2* packed8 = reinterpret_cast<const uint2*>(packed16);

    uint2 q0, q1;
    if ((x0 & 1) == 0) {
        uint4 tq = __ldg(packed16 + (idx >> 1));   // even: one 16B load
        q0 = make_uint2(tq.x, tq.y);
        q1 = make_uint2(tq.z, tq.w);
    } else {
        int dx = (x0 < DIM - 1) ? 1 : 0;           // x0=159 -> x1=159
        q0 = __ldg(packed8 + idx);
        q1 = __ldg(packed8 + idx + dx);
    }

    float2 a0 = __half22float2(u32_to_h2(q0.x));   // (v000, v001)
    float2 a1 = __half22float2(u32_to_h2(q0.y));   // (v010, v011)
    float2 b0 = __half22float2(u32_to_h2(q1.x));   // (v100, v101)
    float2 b1 = __half22float2(u32_to_h2(q1.y));   // (v110, v111)

    float c00 = fmaf(wz, a0.y - a0.x, a0.x);
    float c01 = fmaf(wz, a1.y - a1.x, a1.x);
    float c10 = fmaf(wz, b0.y - b0.x, b0.x);
    float c11 = fmaf(wz, b1.y - b1.x, b1.x);

    float p0 = fmaf(wy, c01 - c00, c00);
    float p1 = fmaf(wy, c11 - c10, c10);
    return fmaf(wx, p1 - p0, p0);
}

#define SBLK 4000                        // (NVOX/4) / 256 per batch

__global__ __launch_bounds__(256) void sample_kernel(
    const float* __restrict__ grid, float* __restrict__ out)
{
    int blk = blockIdx.x;
    int b   = blk >= SBLK;
    int e   = ((blk - b * SBLK) * 256 + threadIdx.x) * 4;  // element base

    const uint4* packed16 = b ? g_packedB : g_packedA;

    const float* g = grid + (long long)b * 3 * NVOX + e;
    float4 gx = __ldcs(reinterpret_cast<const float4*>(g));
    float4 gy = __ldcs(reinterpret_cast<const float4*>(g + NVOX));
    float4 gz = __ldcs(reinterpret_cast<const float4*>(g + 2 * NVOX));

    float4 o;
    o.x = sample_one(packed16, gx.x, gy.x, gz.x);
    o.y = sample_one(packed16, gx.y, gy.y, gz.y);
    o.z = sample_one(packed16, gx.z, gy.z, gz.z);
    o.w = sample_one(packed16, gx.w, gy.w, gz.w);

    __stcs(reinterpret_cast<float4*>(out + (long long)b * NVOX + e), o);
}

extern "C" void kernel_launch(void* const* d_in, const int* in_sizes, int n_in,
                              void* d_out, int out_size)
{
    const float* vol  = (const float*)d_in[0];   // input1 [2,1,160,160,160]
    const float* grid = (const float*)d_in[1];   // input2 [2,3,160,160,160]
    float* out = (float*)d_out;

    pack_both_kernel<<<2 * PACK_BLOCKS, 256>>>(vol);
    sample_kernel   <<<2 * SBLK,        256>>>(grid, out);
}